// round 12
// baseline (speedup 1.0000x reference)
#include <cuda_runtime.h>
#include <cuda_bf16.h>
#include <math.h>
#include <stdint.h>

#define NN 8192
#define FIN 256
#define DD 128
#define ALPHA 0.2f
#define SPLITS 16
#define BM 128
#define BN 64
#define TILES ((NN / SPLITS) / BN)   // 8

// Scratch (allocation-free rule: __device__ globals).
// H,K: int8 two-level quantized planes + per-row scales. V: bf16 hi/lo planes.
__device__ unsigned char gHq1[(size_t)NN * 128];
__device__ unsigned char gHq2[(size_t)NN * 128];
__device__ unsigned char gKq1[(size_t)NN * 128];
__device__ unsigned char gKq2[(size_t)NN * 128];
__device__ float gScaleH[NN];
__device__ float gScaleK[NN];
__device__ uint4 gVh[(size_t)NN * 16];
__device__ uint4 gVl[(size_t)NN * 16];
// inp split planes: 8192 x 256 -> 128 words/row.
__device__ uint4 gIh[(size_t)NN * 32];
__device__ uint4 gIl[(size_t)NN * 32];
// W split planes: 3 mats x 256 rows x 64 words.
__device__ uint4 gWh[3 * 256 * 16];
__device__ uint4 gWl[3 * 256 * 16];
__device__ float gNum[(size_t)SPLITS * NN * DD];
__device__ float gDen[(size_t)SPLITS * NN];

// ---------------------------------------------------------------------------
// helpers
// ---------------------------------------------------------------------------
__device__ __forceinline__ uint32_t smem_u32(const void* p) {
  uint32_t a;
  asm("{ .reg .u64 t; cvta.to.shared.u64 t, %1; cvt.u32.u64 %0, t; }"
      : "=r"(a) : "l"(p));
  return a;
}
__device__ __forceinline__ uint32_t pack_bf(float a, float b) {
  __nv_bfloat162 r = __floats2bfloat162_rn(a, b);
  return *reinterpret_cast<uint32_t*>(&r);
}

#define LDSM_X4(r0, r1, r2, r3, a)                                            \
  asm volatile("ldmatrix.sync.aligned.m8n8.x4.shared.b16 {%0,%1,%2,%3}, [%4];"\
               : "=r"(r0), "=r"(r1), "=r"(r2), "=r"(r3) : "r"(a))
#define LDSM_X4T(r0, r1, r2, r3, a)                                           \
  asm volatile("ldmatrix.sync.aligned.m8n8.x4.trans.shared.b16 {%0,%1,%2,%3}, [%4];" \
               : "=r"(r0), "=r"(r1), "=r"(r2), "=r"(r3) : "r"(a))

__device__ __forceinline__ void mma_bf16(float* d, const uint32_t* a,
                                         uint32_t b0, uint32_t b1) {
  asm volatile(
      "mma.sync.aligned.m16n8k16.row.col.f32.bf16.bf16.f32 "
      "{%0,%1,%2,%3}, {%4,%5,%6,%7}, {%8,%9}, {%0,%1,%2,%3};"
      : "+f"(d[0]), "+f"(d[1]), "+f"(d[2]), "+f"(d[3])
      : "r"(a[0]), "r"(a[1]), "r"(a[2]), "r"(a[3]), "r"(b0), "r"(b1));
}
__device__ __forceinline__ void mma_s8(int* d, const uint32_t* a,
                                       uint32_t b0, uint32_t b1) {
  asm volatile(
      "mma.sync.aligned.m16n8k32.row.col.s32.s8.s8.s32 "
      "{%0,%1,%2,%3}, {%4,%5,%6,%7}, {%8,%9}, {%0,%1,%2,%3};"
      : "+r"(d[0]), "+r"(d[1]), "+r"(d[2]), "+r"(d[3])
      : "r"(a[0]), "r"(a[1]), "r"(a[2]), "r"(a[3]), "r"(b0), "r"(b1));
}

__device__ __forceinline__ void cp16(uint32_t dst, const void* src) {
  asm volatile("cp.async.cg.shared.global [%0], [%1], 16;" :: "r"(dst), "l"(src));
}
#define CP_COMMIT() asm volatile("cp.async.commit_group;" ::: "memory")
#define CP_WAIT1()  asm volatile("cp.async.wait_group 1;" ::: "memory")

// ---------------------------------------------------------------------------
// Kernel 0: split fp32 inputs into packed bf16 hi/lo planes (inp + W).
// ---------------------------------------------------------------------------
__global__ __launch_bounds__(256) void split_kernel(
    const float* __restrict__ inp, const float* __restrict__ W0,
    const float* __restrict__ W1, const float* __restrict__ W2) {
  int idx = blockIdx.x * 256 + threadIdx.x;
  const float* src;
  uint32_t* dh;
  uint32_t* dl;
  int off;
  if (idx < 1048576) {
    src = inp; off = idx;
    dh = (uint32_t*)gIh; dl = (uint32_t*)gIl;
  } else {
    int j = idx - 1048576;
    int mat = j / 16384;
    off = j % 16384;
    src = (mat == 0) ? W0 : (mat == 1) ? W1 : W2;
    dh = (uint32_t*)gWh + mat * 16384;
    dl = (uint32_t*)gWl + mat * 16384;
  }
  float2 v = *(const float2*)(src + 2 * (size_t)off);
  float h0 = __bfloat162float(__float2bfloat16(v.x));
  float h1 = __bfloat162float(__float2bfloat16(v.y));
  dh[off] = pack_bf(h0, h1);
  dl[off] = pack_bf(v.x - h0, v.y - h1);
}

// ---------------------------------------------------------------------------
// Kernel A: projections via warp mma.sync bf16 hi/lo (3-term).
// mat 0/1 (H/K): epilogue quantizes rows to two-level int8 + per-row scale.
// mat 2 (V): epilogue writes bf16 hi/lo planes.
// ---------------------------------------------------------------------------
#define PSTG 27648
#define PSMEM 55296
__global__ void __launch_bounds__(128, 1) proj_kernel() {
  extern __shared__ char smem[];
  uint32_t sb = smem_u32(smem);
  int t = threadIdx.x, w = t >> 5, lane = t & 31;
  int g = lane >> 2, tig = lane & 3;
  int q = lane >> 3, r = lane & 7;
  int rowbase = blockIdx.x * 64;
  int mat = blockIdx.y;
  const uint4* Wh = gWh + mat * 256 * 16;
  const uint4* Wl = gWl + mat * 256 * 16;

  uint32_t offA = (uint32_t)((w * 16 + (q & 1) * 8 + r) * 80 + (q >> 1) * 16);
  uint32_t offB = (uint32_t)(10240 + ((q & 1) * 8 + r) * 272 + (q >> 1) * 16);

  auto load_chunk = [&](int s, int c) {
    uint32_t base = sb + (uint32_t)(s * PSTG);
#pragma unroll
    for (int i = 0; i < 4; i++) {
      int idx = t + i * 128;
      int plane = idx >> 8, row = (idx >> 2) & 63, ch = idx & 3;
      const uint4* srcp = (plane ? gIl : gIh) + (size_t)(rowbase + row) * 32 + c * 4 + ch;
      cp16(base + plane * 5120 + row * 80 + ch * 16, srcp);
    }
#pragma unroll
    for (int i = 0; i < 8; i++) {
      int idx = t + i * 128;
      int plane = idx >> 9, row = (idx >> 4) & 31, ch = idx & 15;
      const uint4* srcp = (plane ? Wl : Wh) + (size_t)(c * 32 + row) * 16 + ch;
      cp16(base + 10240 + plane * 8704 + row * 272 + ch * 16, srcp);
    }
  };

  load_chunk(0, 0); CP_COMMIT();
  load_chunk(1, 1); CP_COMMIT();

  float oacc[16][4];
#pragma unroll
  for (int c = 0; c < 16; c++)
#pragma unroll
    for (int k = 0; k < 4; k++) oacc[c][k] = 0.f;

  for (int c = 0; c < 8; c++) {
    int s = c & 1;
    CP_WAIT1();
    __syncthreads();
    uint32_t aA = sb + (uint32_t)(s * PSTG) + offA;
    uint32_t aB = sb + (uint32_t)(s * PSTG) + offB;
#pragma unroll
    for (int kk = 0; kk < 2; kk++) {
      uint32_t ah[4], al[4];
      LDSM_X4(ah[0], ah[1], ah[2], ah[3], aA + kk * 32);
      LDSM_X4(al[0], al[1], al[2], al[3], aA + 5120 + kk * 32);
#pragma unroll
      for (int np = 0; np < 8; np++) {
        uint32_t bh[4], bl[4];
        uint32_t boff = (uint32_t)(kk * 4352 + np * 32);
        LDSM_X4T(bh[0], bh[1], bh[2], bh[3], aB + boff);
        LDSM_X4T(bl[0], bl[1], bl[2], bl[3], aB + 8704 + boff);
        mma_bf16(oacc[2 * np], ah, bh[0], bh[1]);
        mma_bf16(oacc[2 * np], ah, bl[0], bl[1]);
        mma_bf16(oacc[2 * np], al, bh[0], bh[1]);
        mma_bf16(oacc[2 * np + 1], ah, bh[2], bh[3]);
        mma_bf16(oacc[2 * np + 1], ah, bl[2], bl[3]);
        mma_bf16(oacc[2 * np + 1], al, bh[2], bh[3]);
      }
    }
    __syncthreads();
    if (c + 2 < 8) load_chunk(s, c + 2);
    CP_COMMIT();
  }

  int row0 = rowbase + w * 16 + g;
  if (mat == 2) {
    // V: bf16 hi/lo packed planes
    uint32_t* Ph = (uint32_t*)gVh;
    uint32_t* Pl = (uint32_t*)gVl;
    size_t r0w = (size_t)row0 * 64;
    size_t r8w = r0w + 8 * 64;
#pragma unroll
    for (int np = 0; np < 8; np++) {
#pragma unroll
      for (int half = 0; half < 2; half++) {
        float* d = oacc[2 * np + half];
        int word = np * 8 + half * 4 + tig;
        float h0 = __bfloat162float(__float2bfloat16(d[0]));
        float h1 = __bfloat162float(__float2bfloat16(d[1]));
        float h2 = __bfloat162float(__float2bfloat16(d[2]));
        float h3 = __bfloat162float(__float2bfloat16(d[3]));
        Ph[r0w + word] = pack_bf(h0, h1);
        Pl[r0w + word] = pack_bf(d[0] - h0, d[1] - h1);
        Ph[r8w + word] = pack_bf(h2, h3);
        Pl[r8w + word] = pack_bf(d[2] - h2, d[3] - h3);
      }
    }
  } else {
    // H/K: two-level int8 quantization with per-row scale
    float m0 = 0.f, m8 = 0.f;
#pragma unroll
    for (int c = 0; c < 16; c++) {
      m0 = fmaxf(m0, fmaxf(fabsf(oacc[c][0]), fabsf(oacc[c][1])));
      m8 = fmaxf(m8, fmaxf(fabsf(oacc[c][2]), fabsf(oacc[c][3])));
    }
    m0 = fmaxf(m0, __shfl_xor_sync(0xffffffffu, m0, 1));
    m0 = fmaxf(m0, __shfl_xor_sync(0xffffffffu, m0, 2));
    m8 = fmaxf(m8, __shfl_xor_sync(0xffffffffu, m8, 1));
    m8 = fmaxf(m8, __shfl_xor_sync(0xffffffffu, m8, 2));
    float s1a = (m0 > 0.f) ? m0 * (1.f / 127.f) : 1.f;
    float i1a = (m0 > 0.f) ? 127.f / m0 : 0.f;
    float i2a = 254.f / s1a;
    float s1b = (m8 > 0.f) ? m8 * (1.f / 127.f) : 1.f;
    float i1b = (m8 > 0.f) ? 127.f / m8 : 0.f;
    float i2b = 254.f / s1b;
    unsigned char* Q1 = mat ? gKq1 : gHq1;
    unsigned char* Q2 = mat ? gKq2 : gHq2;
    float* Sc = mat ? gScaleK : gScaleH;
    if (tig == 0) { Sc[row0] = s1a; Sc[row0 + 8] = s1b; }
    size_t b0 = (size_t)row0 * 128;
    size_t b8 = b0 + 8 * 128;
#pragma unroll
    for (int np = 0; np < 8; np++) {
#pragma unroll
      for (int half = 0; half < 2; half++) {
        float* d = oacc[2 * np + half];
        int off2 = (np * 8 + half * 4 + tig) * 2;
        int qa = __float2int_rn(d[0] * i1a);
        int qa2 = __float2int_rn(fmaf((float)-qa, s1a, d[0]) * i2a);
        int qb = __float2int_rn(d[1] * i1a);
        int qb2 = __float2int_rn(fmaf((float)-qb, s1a, d[1]) * i2a);
        int qc = __float2int_rn(d[2] * i1b);
        int qc2 = __float2int_rn(fmaf((float)-qc, s1b, d[2]) * i2b);
        int qd = __float2int_rn(d[3] * i1b);
        int qd2 = __float2int_rn(fmaf((float)-qd, s1b, d[3]) * i2b);
        *(unsigned short*)(Q1 + b0 + off2) =
            (unsigned short)((qa & 0xFF) | ((qb & 0xFF) << 8));
        *(unsigned short*)(Q2 + b0 + off2) =
            (unsigned short)((qa2 & 0xFF) | ((qb2 & 0xFF) << 8));
        *(unsigned short*)(Q1 + b8 + off2) =
            (unsigned short)((qc & 0xFF) | ((qd & 0xFF) << 8));
        *(unsigned short*)(Q2 + b8 + off2) =
            (unsigned short)((qc2 & 0xFF) | ((qd2 & 0xFF) << 8));
      }
    }
  }
}

// ---------------------------------------------------------------------------
// Kernel B: fused attention. S via int8 m16n8k32 (exact 15-bit, 4 MMAs/32k),
// PV via bf16 3-term. 3-stage cp.async KV buffer.
// Stage: Kq1 0 (64x144B) / Kq2 9216 / Kscale 18432 (256B) / Vhi 18688 /
// Vlo 36096; stage size 53504.
// ---------------------------------------------------------------------------
#define TRS 272
#define STAGE 53504
#define SMEM_BYTES 160512           // 3 stages

__device__ __forceinline__ void load_kv_async(uint32_t sb, int s, int cb, int t) {
  uint32_t base = sb + (uint32_t)(s * STAGE);
#pragma unroll
  for (int i = 0; i < 13; i++) {
    int idx = t + i * 256;
    if (idx < 1024) {
      int plane = idx >> 9, row = (idx >> 3) & 63, ch = idx & 7;
      const unsigned char* src =
          (plane ? gKq2 : gKq1) + (size_t)(cb + row) * 128 + ch * 16;
      cp16(base + plane * 9216 + row * 144 + ch * 16, src);
    } else if (idx < 1040) {
      int ch = idx - 1024;
      cp16(base + 18432 + ch * 16, (const char*)(gScaleK + cb) + ch * 16);
    } else if (idx < 3088) {
      int v = idx - 1040;
      int plane = v >> 10, row = (v >> 4) & 63, ch = v & 15;
      const uint4* src = (plane ? gVl : gVh) + (size_t)(cb + row) * 16 + ch;
      cp16(base + 18688 + plane * 17408 + row * 272 + ch * 16, src);
    }
  }
}

__global__ void __launch_bounds__(256, 1) attn_kernel(const int* __restrict__ adj) {
  extern __shared__ char smem[];
  uint32_t sb = smem_u32(smem);
  int t = threadIdx.x, w = t >> 5, lane = t & 31;
  int g = lane >> 2, tig = lane & 3;
  int rowbase = blockIdx.x * BM;
  int colstart = blockIdx.y * (NN / SPLITS);
  int q = lane >> 3, r = lane & 7;
  uint32_t offBq = (uint32_t)((lane >> 2) * 144 + 4 * (lane & 3));
  uint32_t offV = (uint32_t)(18688 + ((q & 1) * 8 + r) * 272 + (q >> 1) * 16);
  int row0 = rowbase + w * 16 + g;

  load_kv_async(sb, 0, colstart, t);
  CP_COMMIT();
  load_kv_async(sb, 1, colstart + BN, t);
  CP_COMMIT();

  // H int8 fragments via direct LDG (A-fragment layout == natural byte layout)
  uint32_t aq1[4][4], aq2[4][4];
  {
    const unsigned char* H1 = gHq1;
    const unsigned char* H2 = gHq2;
    size_t b0 = (size_t)row0 * 128;
    size_t b8 = b0 + 8 * 128;
#pragma unroll
    for (int c = 0; c < 4; c++) {
      int off = c * 32 + 4 * tig;
      aq1[c][0] = *(const uint32_t*)(H1 + b0 + off);
      aq1[c][1] = *(const uint32_t*)(H1 + b8 + off);
      aq1[c][2] = *(const uint32_t*)(H1 + b0 + off + 16);
      aq1[c][3] = *(const uint32_t*)(H1 + b8 + off + 16);
      aq2[c][0] = *(const uint32_t*)(H2 + b0 + off);
      aq2[c][1] = *(const uint32_t*)(H2 + b8 + off);
      aq2[c][2] = *(const uint32_t*)(H2 + b0 + off + 16);
      aq2[c][3] = *(const uint32_t*)(H2 + b8 + off + 16);
    }
  }
  float sHg = gScaleH[row0];
  float sHg8 = gScaleH[row0 + 8];

  float oacc[16][4];
#pragma unroll
  for (int c = 0; c < 16; c++)
#pragma unroll
    for (int k = 0; k < 4; k++) oacc[c][k] = 0.f;
  float den0 = 0.f, den1 = 0.f;

  const int* arow0 = adj + (size_t)row0 * NN;
  const int* arow1 = arow0 + (size_t)8 * NN;
  const float C1 = 1.f / 254.f;
  const float C2 = 1.f / 64516.f;

  int s3 = 0;
  for (int tt = 0; tt < TILES; tt++) {
    int cb = colstart + tt * BN;
    CP_WAIT1();
    __syncthreads();
    if (tt + 2 < TILES) load_kv_async(sb, (tt + 2) % 3, colstart + (tt + 2) * BN, t);
    CP_COMMIT();

    const char* kstage = smem + s3 * STAGE;
    uint32_t aVh = sb + (uint32_t)(s3 * STAGE) + offV;

#pragma unroll
    for (int half = 0; half < 2; half++) {
      // adj masks for this half's 32 cols (latency hidden under S MMAs)
      int2 am[8];
#pragma unroll
      for (int n = 0; n < 4; n++) {
        am[n] = *(const int2*)(arow0 + cb + half * 32 + n * 8 + 2 * tig);
        am[n + 4] = *(const int2*)(arow1 + cb + half * 32 + n * 8 + 2 * tig);
      }

      // ---- S int8: D1=Q1Q1, D2=Q1Q2+Q2Q1, D3=Q2Q2 ----
      int D1[4][4], D2[4][4], D3[4][4];
#pragma unroll
      for (int nb = 0; nb < 4; nb++)
#pragma unroll
        for (int k = 0; k < 4; k++) { D1[nb][k] = 0; D2[nb][k] = 0; D3[nb][k] = 0; }

#pragma unroll
      for (int c = 0; c < 4; c++) {
#pragma unroll
        for (int nb = 0; nb < 4; nb++) {
          const char* ad = kstage + (half * 4 + nb) * 1152 + c * 32 + offBq;
          uint32_t b0a = *(const uint32_t*)(ad);
          uint32_t b1a = *(const uint32_t*)(ad + 16);
          uint32_t b0b = *(const uint32_t*)(ad + 9216);
          uint32_t b1b = *(const uint32_t*)(ad + 9232);
          mma_s8(D1[nb], aq1[c], b0a, b1a);
          mma_s8(D2[nb], aq1[c], b0b, b1b);
          mma_s8(D2[nb], aq2[c], b0a, b1a);
          mma_s8(D3[nb], aq2[c], b0b, b1b);
        }
      }

      // ---- dequant to fp32 logits ----
      float sacc[4][4];
#pragma unroll
      for (int nb = 0; nb < 4; nb++) {
        float2 sk = *(const float2*)(kstage + 18432 +
                                     ((half * 4 + nb) * 8 + 2 * tig) * 4);
        float f0 = (float)D1[nb][0] + (float)D2[nb][0] * C1 + (float)D3[nb][0] * C2;
        float f1 = (float)D1[nb][1] + (float)D2[nb][1] * C1 + (float)D3[nb][1] * C2;
        float f2 = (float)D1[nb][2] + (float)D2[nb][2] * C1 + (float)D3[nb][2] * C2;
        float f3 = (float)D1[nb][3] + (float)D2[nb][3] * C1 + (float)D3[nb][3] * C2;
        sacc[nb][0] = f0 * (sHg * sk.x);
        sacc[nb][1] = f1 * (sHg * sk.y);
        sacc[nb][2] = f2 * (sHg8 * sk.x);
        sacc[nb][3] = f3 * (sHg8 * sk.y);
      }

      // ---- leakyrelu + adj mask + exp -> P fragments -> PV (bf16 3-term) ----
#pragma unroll
      for (int kkl = 0; kkl < 2; kkl++) {
        uint32_t phi[4], plo[4];
#pragma unroll
        for (int cp = 0; cp < 2; cp++) {
          int nloc = 2 * kkl + cp;
          int2 m0 = am[nloc];
          int2 m1 = am[nloc + 4];
          float e0 = sacc[nloc][0], e1 = sacc[nloc][1];
          float e2 = sacc[nloc][2], e3 = sacc[nloc][3];
          e0 = e0 > 0.f ? e0 : ALPHA * e0;
          e1 = e1 > 0.f ? e1 : ALPHA * e1;
          e2 = e2 > 0.f ? e2 : ALPHA * e2;
          e3 = e3 > 0.f ? e3 : ALPHA * e3;
          float p0 = (m0.x > 0) ? __expf(e0) : 0.f;
          float p1 = (m0.y > 0) ? __expf(e1) : 0.f;
          float p2 = (m1.x > 0) ? __expf(e2) : 0.f;
          float p3 = (m1.y > 0) ? __expf(e3) : 0.f;
          den0 += p0 + p1;
          den1 += p2 + p3;
          float h0 = __bfloat162float(__float2bfloat16(p0));
          float h1 = __bfloat162float(__float2bfloat16(p1));
          float h2 = __bfloat162float(__float2bfloat16(p2));
          float h3 = __bfloat162float(__float2bfloat16(p3));
          phi[2 * cp + 0] = pack_bf(h0, h1);
          phi[2 * cp + 1] = pack_bf(h2, h3);
          plo[2 * cp + 0] = pack_bf(p0 - h0, p1 - h1);
          plo[2 * cp + 1] = pack_bf(p2 - h2, p3 - h3);
        }
        int kkg = 2 * half + kkl;
#pragma unroll
        for (int cp = 0; cp < 8; cp++) {
          uint32_t vh[4], vl[4];
          uint32_t voff = (uint32_t)(kkg * (16 * TRS) + cp * 32);
          LDSM_X4T(vh[0], vh[1], vh[2], vh[3], aVh + voff);
          LDSM_X4T(vl[0], vl[1], vl[2], vl[3], aVh + 17408 + voff);
          mma_bf16(oacc[2 * cp], phi, vh[0], vh[1]);
          mma_bf16(oacc[2 * cp], phi, vl[0], vl[1]);
          mma_bf16(oacc[2 * cp], plo, vh[0], vh[1]);
          mma_bf16(oacc[2 * cp + 1], phi, vh[2], vh[3]);
          mma_bf16(oacc[2 * cp + 1], phi, vl[2], vl[3]);
          mma_bf16(oacc[2 * cp + 1], plo, vh[2], vh[3]);
        }
      }
    }
    s3 = (s3 == 2) ? 0 : s3 + 1;
  }

  // ---- epilogue: den (quad reduce) + O partials ----
  den0 += __shfl_xor_sync(0xffffffffu, den0, 1);
  den0 += __shfl_xor_sync(0xffffffffu, den0, 2);
  den1 += __shfl_xor_sync(0xffffffffu, den1, 1);
  den1 += __shfl_xor_sync(0xffffffffu, den1, 2);
  if (tig == 0) {
    gDen[(size_t)blockIdx.y * NN + row0] = den0;
    gDen[(size_t)blockIdx.y * NN + row0 + 8] = den1;
  }
  float* base0 = gNum + ((size_t)blockIdx.y * NN + row0) * DD;
  float* base1 = base0 + (size_t)8 * DD;
#pragma unroll
  for (int c = 0; c < 16; c++) {
    *(float2*)(base0 + c * 8 + 2 * tig) = make_float2(oacc[c][0], oacc[c][1]);
    *(float2*)(base1 + c * 8 + 2 * tig) = make_float2(oacc[c][2], oacc[c][3]);
  }
}

// ---------------------------------------------------------------------------
// Kernel C: combine split partials, divide, ELU (float4 vectorized).
// ---------------------------------------------------------------------------
__global__ __launch_bounds__(256) void reduce_kernel(float* __restrict__ out) {
  int idx = blockIdx.x * 256 + threadIdx.x;
  int row = idx >> 5;
  int c4 = (idx & 31) * 4;
  float4 num = make_float4(0.f, 0.f, 0.f, 0.f);
  float den = 0.f;
#pragma unroll
  for (int s = 0; s < SPLITS; s++) {
    float4 v = *(const float4*)(gNum + ((size_t)s * NN + row) * DD + c4);
    num.x += v.x; num.y += v.y; num.z += v.z; num.w += v.w;
    den += gDen[(size_t)s * NN + row];
  }
  float inv = 1.f / den;
  float h0 = num.x * inv, h1 = num.y * inv, h2 = num.z * inv, h3 = num.w * inv;
  float4 o;
  o.x = (h0 > 0.f) ? h0 : expm1f(h0);
  o.y = (h1 > 0.f) ? h1 : expm1f(h1);
  o.z = (h2 > 0.f) ? h2 : expm1f(h2);
  o.w = (h3 > 0.f) ? h3 : expm1f(h3);
  *(float4*)(out + (size_t)row * DD + c4) = o;
}

// ---------------------------------------------------------------------------
extern "C" void kernel_launch(void* const* d_in, const int* in_sizes, int n_in,
                              void* d_out, int out_size) {
  const float* inp = (const float*)d_in[0];
  const int* adj = (const int*)d_in[1];
  const float* W = (const float*)d_in[2];
  const float* W2 = (const float*)d_in[3];
  const float* W3 = (const float*)d_in[4];
  float* out = (float*)d_out;

  split_kernel<<<4288, 256>>>(inp, W, W2, W3);

  cudaFuncSetAttribute(proj_kernel, cudaFuncAttributeMaxDynamicSharedMemorySize,
                       PSMEM);
  proj_kernel<<<dim3(NN / 64, 3), 128, PSMEM>>>();

  cudaFuncSetAttribute(attn_kernel, cudaFuncAttributeMaxDynamicSharedMemorySize,
                       SMEM_BYTES);
  attn_kernel<<<dim3(NN / BM, SPLITS), 256, SMEM_BYTES>>>(adj);

  reduce_kernel<<<(NN * DD) / 1024, 256>>>(out);
}

// round 13
// speedup vs baseline: 1.8955x; 1.8955x over previous
#include <cuda_runtime.h>
#include <cuda_fp16.h>
#include <math.h>
#include <stdint.h>

#define NN 8192
#define FIN 256
#define DD 128
#define ALPHA 0.2f
#define SPLITS 16
#define BM 128
#define BN 64
#define TILES ((NN / SPLITS) / BN)   // 8

// Scratch (allocation-free rule: __device__ globals).
// H,K: fp16 hi/lo packed planes; V: single fp16 plane. 16 uint4/row = 128 fp16.
__device__ uint4 gHh[(size_t)NN * 16];
__device__ uint4 gHl[(size_t)NN * 16];
__device__ uint4 gKh[(size_t)NN * 16];
__device__ uint4 gKl[(size_t)NN * 16];
__device__ uint4 gV[(size_t)NN * 16];
// inp split planes: 8192 x 256 -> 128 words/row.
__device__ uint4 gIh[(size_t)NN * 32];
__device__ uint4 gIl[(size_t)NN * 32];
// W split planes: 3 mats x 256 rows x 64 words.
__device__ uint4 gWh[3 * 256 * 16];
__device__ uint4 gWl[3 * 256 * 16];
__device__ float gNum[(size_t)SPLITS * NN * DD];
__device__ float gDen[(size_t)SPLITS * NN];
__device__ float gM[(size_t)SPLITS * NN];

// ---------------------------------------------------------------------------
// helpers
// ---------------------------------------------------------------------------
__device__ __forceinline__ uint32_t smem_u32(const void* p) {
  uint32_t a;
  asm("{ .reg .u64 t; cvta.to.shared.u64 t, %1; cvt.u32.u64 %0, t; }"
      : "=r"(a) : "l"(p));
  return a;
}
__device__ __forceinline__ uint32_t pack_h2(float a, float b) {
  __half2 r = __floats2half2_rn(a, b);
  return *reinterpret_cast<uint32_t*>(&r);
}
__device__ __forceinline__ float h_round(float x) {
  return __half2float(__float2half_rn(x));
}

#define LDSM_X4(r0, r1, r2, r3, a)                                            \
  asm volatile("ldmatrix.sync.aligned.m8n8.x4.shared.b16 {%0,%1,%2,%3}, [%4];"\
               : "=r"(r0), "=r"(r1), "=r"(r2), "=r"(r3) : "r"(a))
#define LDSM_X4T(r0, r1, r2, r3, a)                                           \
  asm volatile("ldmatrix.sync.aligned.m8n8.x4.trans.shared.b16 {%0,%1,%2,%3}, [%4];" \
               : "=r"(r0), "=r"(r1), "=r"(r2), "=r"(r3) : "r"(a))

__device__ __forceinline__ void mma_f16(float* d, const uint32_t* a,
                                        uint32_t b0, uint32_t b1) {
  asm volatile(
      "mma.sync.aligned.m16n8k16.row.col.f32.f16.f16.f32 "
      "{%0,%1,%2,%3}, {%4,%5,%6,%7}, {%8,%9}, {%0,%1,%2,%3};"
      : "+f"(d[0]), "+f"(d[1]), "+f"(d[2]), "+f"(d[3])
      : "r"(a[0]), "r"(a[1]), "r"(a[2]), "r"(a[3]), "r"(b0), "r"(b1));
}

__device__ __forceinline__ void cp16(uint32_t dst, const void* src) {
  asm volatile("cp.async.cg.shared.global [%0], [%1], 16;" :: "r"(dst), "l"(src));
}
#define CP_COMMIT() asm volatile("cp.async.commit_group;" ::: "memory")
#define CP_WAIT1()  asm volatile("cp.async.wait_group 1;" ::: "memory")

// ---------------------------------------------------------------------------
// Kernel 0: split fp32 inputs into packed fp16 hi/lo planes (inp + W).
// ---------------------------------------------------------------------------
__global__ __launch_bounds__(256) void split_kernel(
    const float* __restrict__ inp, const float* __restrict__ W0,
    const float* __restrict__ W1, const float* __restrict__ W2) {
  int idx = blockIdx.x * 256 + threadIdx.x;
  const float* src;
  uint32_t* dh;
  uint32_t* dl;
  int off;
  if (idx < 1048576) {
    src = inp; off = idx;
    dh = (uint32_t*)gIh; dl = (uint32_t*)gIl;
  } else {
    int j = idx - 1048576;
    int mat = j / 16384;
    off = j % 16384;
    src = (mat == 0) ? W0 : (mat == 1) ? W1 : W2;
    dh = (uint32_t*)gWh + mat * 16384;
    dl = (uint32_t*)gWl + mat * 16384;
  }
  float2 v = *(const float2*)(src + 2 * (size_t)off);
  float h0 = h_round(v.x);
  float h1 = h_round(v.y);
  dh[off] = pack_h2(h0, h1);
  dl[off] = pack_h2(v.x - h0, v.y - h1);
}

// ---------------------------------------------------------------------------
// Kernel A: projections via warp mma.sync fp16 hi/lo (3-term).
// mat 0/1 (H/K): epilogue writes fp16 hi/lo planes.
// mat 2 (V): epilogue writes single fp16 plane.
// ---------------------------------------------------------------------------
#define PSTG 27648
#define PSMEM 55296
__global__ void __launch_bounds__(128, 1) proj_kernel() {
  extern __shared__ char smem[];
  uint32_t sb = smem_u32(smem);
  int t = threadIdx.x, w = t >> 5, lane = t & 31;
  int g = lane >> 2, tig = lane & 3;
  int q = lane >> 3, r = lane & 7;
  int rowbase = blockIdx.x * 64;
  int mat = blockIdx.y;
  const uint4* Wh = gWh + mat * 256 * 16;
  const uint4* Wl = gWl + mat * 256 * 16;

  uint32_t offA = (uint32_t)((w * 16 + (q & 1) * 8 + r) * 80 + (q >> 1) * 16);
  uint32_t offB = (uint32_t)(10240 + ((q & 1) * 8 + r) * 272 + (q >> 1) * 16);

  auto load_chunk = [&](int s, int c) {
    uint32_t base = sb + (uint32_t)(s * PSTG);
#pragma unroll
    for (int i = 0; i < 4; i++) {
      int idx = t + i * 128;
      int plane = idx >> 8, row = (idx >> 2) & 63, ch = idx & 3;
      const uint4* srcp = (plane ? gIl : gIh) + (size_t)(rowbase + row) * 32 + c * 4 + ch;
      cp16(base + plane * 5120 + row * 80 + ch * 16, srcp);
    }
#pragma unroll
    for (int i = 0; i < 8; i++) {
      int idx = t + i * 128;
      int plane = idx >> 9, row = (idx >> 4) & 31, ch = idx & 15;
      const uint4* srcp = (plane ? Wl : Wh) + (size_t)(c * 32 + row) * 16 + ch;
      cp16(base + 10240 + plane * 8704 + row * 272 + ch * 16, srcp);
    }
  };

  load_chunk(0, 0); CP_COMMIT();
  load_chunk(1, 1); CP_COMMIT();

  float oacc[16][4];
#pragma unroll
  for (int c = 0; c < 16; c++)
#pragma unroll
    for (int k = 0; k < 4; k++) oacc[c][k] = 0.f;

  for (int c = 0; c < 8; c++) {
    int s = c & 1;
    CP_WAIT1();
    __syncthreads();
    uint32_t aA = sb + (uint32_t)(s * PSTG) + offA;
    uint32_t aB = sb + (uint32_t)(s * PSTG) + offB;
#pragma unroll
    for (int kk = 0; kk < 2; kk++) {
      uint32_t ah[4], al[4];
      LDSM_X4(ah[0], ah[1], ah[2], ah[3], aA + kk * 32);
      LDSM_X4(al[0], al[1], al[2], al[3], aA + 5120 + kk * 32);
#pragma unroll
      for (int np = 0; np < 8; np++) {
        uint32_t bh[4], bl[4];
        uint32_t boff = (uint32_t)(kk * 4352 + np * 32);
        LDSM_X4T(bh[0], bh[1], bh[2], bh[3], aB + boff);
        LDSM_X4T(bl[0], bl[1], bl[2], bl[3], aB + 8704 + boff);
        mma_f16(oacc[2 * np], ah, bh[0], bh[1]);
        mma_f16(oacc[2 * np], ah, bl[0], bl[1]);
        mma_f16(oacc[2 * np], al, bh[0], bh[1]);
        mma_f16(oacc[2 * np + 1], ah, bh[2], bh[3]);
        mma_f16(oacc[2 * np + 1], ah, bl[2], bl[3]);
        mma_f16(oacc[2 * np + 1], al, bh[2], bh[3]);
      }
    }
    __syncthreads();
    if (c + 2 < 8) load_chunk(s, c + 2);
    CP_COMMIT();
  }

  int row0 = rowbase + w * 16 + g;
  size_t r0w = (size_t)row0 * 64;
  size_t r8w = r0w + 8 * 64;
  if (mat == 2) {
    // V: single fp16 plane
    uint32_t* Pv = (uint32_t*)gV;
#pragma unroll
    for (int np = 0; np < 8; np++) {
#pragma unroll
      for (int half = 0; half < 2; half++) {
        float* d = oacc[2 * np + half];
        int word = np * 8 + half * 4 + tig;
        Pv[r0w + word] = pack_h2(d[0], d[1]);
        Pv[r8w + word] = pack_h2(d[2], d[3]);
      }
    }
  } else {
    // H/K: fp16 hi/lo planes
    uint32_t* Ph = (uint32_t*)(mat ? gKh : gHh);
    uint32_t* Pl = (uint32_t*)(mat ? gKl : gHl);
#pragma unroll
    for (int np = 0; np < 8; np++) {
#pragma unroll
      for (int half = 0; half < 2; half++) {
        float* d = oacc[2 * np + half];
        int word = np * 8 + half * 4 + tig;
        float h0 = h_round(d[0]);
        float h1 = h_round(d[1]);
        float h2 = h_round(d[2]);
        float h3 = h_round(d[3]);
        Ph[r0w + word] = pack_h2(h0, h1);
        Pl[r0w + word] = pack_h2(d[0] - h0, d[1] - h1);
        Ph[r8w + word] = pack_h2(h2, h3);
        Pl[r8w + word] = pack_h2(d[2] - h2, d[3] - h3);
      }
    }
  }
}

// ---------------------------------------------------------------------------
// Kernel B: fused attention, fp16. S = 3-term hi/lo (192 MMA/tile),
// online row-max softmax, PV = single-P x single-V (64 MMA/tile).
// Stage: Khi 0 / Klo 17408 / V 34816; 64 rows, stride 272; stage 52224.
// ---------------------------------------------------------------------------
#define TRS 272
#define STAGE 52224
#define SMEM_BYTES 156672           // 3 stages

__device__ __forceinline__ void load_kv_async(uint32_t sb, int s, int cb, int t) {
  uint32_t base = sb + (uint32_t)(s * STAGE);
#pragma unroll
  for (int i = 0; i < 12; i++) {
    int idx = t + i * 256;                 // 0..3071
    if (idx < 2048) {
      int plane = idx >> 10, row = (idx >> 4) & 63, ch = idx & 15;
      const uint4* src = (plane ? gKl : gKh) + (size_t)(cb + row) * 16 + ch;
      cp16(base + plane * 17408 + row * TRS + ch * 16, src);
    } else {
      int v = idx - 2048;
      int row = (v >> 4) & 63, ch = v & 15;
      cp16(base + 34816 + row * TRS + ch * 16, gV + (size_t)(cb + row) * 16 + ch);
    }
  }
}

__global__ void __launch_bounds__(256, 1) attn_kernel(const int* __restrict__ adj) {
  extern __shared__ char smem[];
  uint32_t sb = smem_u32(smem);
  int t = threadIdx.x, w = t >> 5, lane = t & 31;
  int g = lane >> 2, tig = lane & 3;
  int rowbase = blockIdx.x * BM;
  int colstart = blockIdx.y * (NN / SPLITS);
  int q = lane >> 3, r = lane & 7;
  uint32_t offB = (uint32_t)(((q >> 1) * 8 + r) * TRS + (q & 1) * 16);
  uint32_t offV = (uint32_t)(34816 + ((q & 1) * 8 + r) * TRS + (q >> 1) * 16);
  int row0 = rowbase + w * 16 + g;

  load_kv_async(sb, 0, colstart, t);
  CP_COMMIT();
  load_kv_async(sb, 1, colstart + BN, t);
  CP_COMMIT();

  // H fragments via direct LDG (A-fragment layout == packed word layout)
  uint32_t ahf[8][4], alf[8][4];
  {
    const uint32_t* Hh = (const uint32_t*)gHh;
    const uint32_t* Hl = (const uint32_t*)gHl;
    size_t b0 = (size_t)row0 * 64;
    size_t b8 = b0 + 8 * 64;
#pragma unroll
    for (int kk = 0; kk < 8; kk++) {
      int wd = kk * 8 + tig;
      ahf[kk][0] = Hh[b0 + wd];     ahf[kk][1] = Hh[b8 + wd];
      ahf[kk][2] = Hh[b0 + wd + 4]; ahf[kk][3] = Hh[b8 + wd + 4];
      alf[kk][0] = Hl[b0 + wd];     alf[kk][1] = Hl[b8 + wd];
      alf[kk][2] = Hl[b0 + wd + 4]; alf[kk][3] = Hl[b8 + wd + 4];
    }
  }

  float oacc[16][4];
#pragma unroll
  for (int c = 0; c < 16; c++)
#pragma unroll
    for (int k = 0; k < 4; k++) oacc[c][k] = 0.f;
  float den0 = 0.f, den1 = 0.f;
  float m0 = -1e30f, m1 = -1e30f;

  const int* arow0 = adj + (size_t)row0 * NN;
  const int* arow1 = arow0 + (size_t)8 * NN;

  int s3 = 0;
  for (int tt = 0; tt < TILES; tt++) {
    int cb = colstart + tt * BN;
    CP_WAIT1();
    __syncthreads();
    if (tt + 2 < TILES) load_kv_async(sb, (tt + 2) % 3, colstart + (tt + 2) * BN, t);
    CP_COMMIT();

    // adj prefetch (hidden under S MMAs)
    int2 am[16];
#pragma unroll
    for (int n = 0; n < 8; n++) {
      am[n] = *(const int2*)(arow0 + cb + n * 8 + 2 * tig);
      am[n + 8] = *(const int2*)(arow1 + cb + n * 8 + 2 * tig);
    }

    uint32_t aBh = sb + (uint32_t)(s3 * STAGE) + offB;
    uint32_t aVh = sb + (uint32_t)(s3 * STAGE) + offV;

    // ---- S = H @ K^T (fp16 hi/lo: hh + hl + lh), A from registers ----
    float sacc[8][4];
#pragma unroll
    for (int c = 0; c < 8; c++)
#pragma unroll
      for (int k = 0; k < 4; k++) sacc[c][k] = 0.f;

#pragma unroll
    for (int kk = 0; kk < 8; kk++) {
#pragma unroll
      for (int np = 0; np < 4; np++) {
        uint32_t bh[4], bl[4];
        uint32_t boff = (uint32_t)(np * (16 * TRS) + kk * 32);
        LDSM_X4(bh[0], bh[1], bh[2], bh[3], aBh + boff);
        LDSM_X4(bl[0], bl[1], bl[2], bl[3], aBh + 17408 + boff);
        mma_f16(sacc[2 * np], ahf[kk], bh[0], bh[1]);
        mma_f16(sacc[2 * np], ahf[kk], bl[0], bl[1]);
        mma_f16(sacc[2 * np], alf[kk], bh[0], bh[1]);
        mma_f16(sacc[2 * np + 1], ahf[kk], bh[2], bh[3]);
        mma_f16(sacc[2 * np + 1], ahf[kk], bl[2], bl[3]);
        mma_f16(sacc[2 * np + 1], alf[kk], bh[2], bh[3]);
      }
    }

    // ---- online max update + rescale ----
    {
      float mt0 = -1e30f, mt1 = -1e30f;
#pragma unroll
      for (int c = 0; c < 8; c++) {
        mt0 = fmaxf(mt0, fmaxf(sacc[c][0], sacc[c][1]));
        mt1 = fmaxf(mt1, fmaxf(sacc[c][2], sacc[c][3]));
      }
      mt0 = fmaxf(mt0, __shfl_xor_sync(0xffffffffu, mt0, 1));
      mt0 = fmaxf(mt0, __shfl_xor_sync(0xffffffffu, mt0, 2));
      mt1 = fmaxf(mt1, __shfl_xor_sync(0xffffffffu, mt1, 1));
      mt1 = fmaxf(mt1, __shfl_xor_sync(0xffffffffu, mt1, 2));
      // leakyrelu is monotone: max(e) = leakyrelu(max(s))
      float e0 = mt0 > 0.f ? mt0 : ALPHA * mt0;
      float e1 = mt1 > 0.f ? mt1 : ALPHA * mt1;
      float m0n = fmaxf(m0, e0);
      float m1n = fmaxf(m1, e1);
      float sc0 = __expf(m0 - m0n);
      float sc1 = __expf(m1 - m1n);
      m0 = m0n; m1 = m1n;
      den0 *= sc0; den1 *= sc1;
#pragma unroll
      for (int c = 0; c < 16; c++) {
        oacc[c][0] *= sc0; oacc[c][1] *= sc0;
        oacc[c][2] *= sc1; oacc[c][3] *= sc1;
      }
    }

    // ---- leakyrelu + adj mask + exp(e-m) -> fp16 P fragment -> PV ----
#pragma unroll
    for (int kk = 0; kk < 4; kk++) {
      uint32_t pw[4];
#pragma unroll
      for (int cp = 0; cp < 2; cp++) {
        int n = 2 * kk + cp;
        int2 mA = am[n];
        int2 mB = am[n + 8];
        float e0 = sacc[n][0], e1 = sacc[n][1], e2 = sacc[n][2], e3 = sacc[n][3];
        e0 = e0 > 0.f ? e0 : ALPHA * e0;
        e1 = e1 > 0.f ? e1 : ALPHA * e1;
        e2 = e2 > 0.f ? e2 : ALPHA * e2;
        e3 = e3 > 0.f ? e3 : ALPHA * e3;
        float p0 = (mA.x > 0) ? __expf(e0 - m0) : 0.f;
        float p1 = (mA.y > 0) ? __expf(e1 - m0) : 0.f;
        float p2 = (mB.x > 0) ? __expf(e2 - m1) : 0.f;
        float p3 = (mB.y > 0) ? __expf(e3 - m1) : 0.f;
        uint32_t wA = pack_h2(p0, p1);
        uint32_t wB = pack_h2(p2, p3);
        // den accumulates the ROUNDED values so num/den stay consistent
        float2 fA = __half22float2(*reinterpret_cast<__half2*>(&wA));
        float2 fB = __half22float2(*reinterpret_cast<__half2*>(&wB));
        den0 += fA.x + fA.y;
        den1 += fB.x + fB.y;
        pw[2 * cp + 0] = wA;
        pw[2 * cp + 1] = wB;
      }
#pragma unroll
      for (int cp = 0; cp < 8; cp++) {
        uint32_t vv[4];
        uint32_t voff = (uint32_t)(kk * (16 * TRS) + cp * 32);
        LDSM_X4T(vv[0], vv[1], vv[2], vv[3], aVh + voff);
        mma_f16(oacc[2 * cp], pw, vv[0], vv[1]);
        mma_f16(oacc[2 * cp + 1], pw, vv[2], vv[3]);
      }
    }
    s3 = (s3 == 2) ? 0 : s3 + 1;
  }

  // ---- epilogue: den (quad reduce) + m + O partials ----
  den0 += __shfl_xor_sync(0xffffffffu, den0, 1);
  den0 += __shfl_xor_sync(0xffffffffu, den0, 2);
  den1 += __shfl_xor_sync(0xffffffffu, den1, 1);
  den1 += __shfl_xor_sync(0xffffffffu, den1, 2);
  if (tig == 0) {
    gDen[(size_t)blockIdx.y * NN + row0] = den0;
    gDen[(size_t)blockIdx.y * NN + row0 + 8] = den1;
    gM[(size_t)blockIdx.y * NN + row0] = m0;
    gM[(size_t)blockIdx.y * NN + row0 + 8] = m1;
  }
  float* base0 = gNum + ((size_t)blockIdx.y * NN + row0) * DD;
  float* base1 = base0 + (size_t)8 * DD;
#pragma unroll
  for (int c = 0; c < 16; c++) {
    *(float2*)(base0 + c * 8 + 2 * tig) = make_float2(oacc[c][0], oacc[c][1]);
    *(float2*)(base1 + c * 8 + 2 * tig) = make_float2(oacc[c][2], oacc[c][3]);
  }
}

// ---------------------------------------------------------------------------
// Kernel C: combine split partials with per-split max weights, divide, ELU.
// ---------------------------------------------------------------------------
__global__ __launch_bounds__(256) void reduce_kernel(float* __restrict__ out) {
  int idx = blockIdx.x * 256 + threadIdx.x;
  int row = idx >> 5;
  int c4 = (idx & 31) * 4;
  float ms[SPLITS];
  float M = -1e30f;
#pragma unroll
  for (int s = 0; s < SPLITS; s++) {
    ms[s] = gM[(size_t)s * NN + row];
    M = fmaxf(M, ms[s]);
  }
  float4 num = make_float4(0.f, 0.f, 0.f, 0.f);
  float den = 0.f;
#pragma unroll
  for (int s = 0; s < SPLITS; s++) {
    float wgt = __expf(ms[s] - M);
    float4 v = *(const float4*)(gNum + ((size_t)s * NN + row) * DD + c4);
    num.x += v.x * wgt; num.y += v.y * wgt;
    num.z += v.z * wgt; num.w += v.w * wgt;
    den += gDen[(size_t)s * NN + row] * wgt;
  }
  float inv = 1.f / den;
  float h0 = num.x * inv, h1 = num.y * inv, h2 = num.z * inv, h3 = num.w * inv;
  float4 o;
  o.x = (h0 > 0.f) ? h0 : expm1f(h0);
  o.y = (h1 > 0.f) ? h1 : expm1f(h1);
  o.z = (h2 > 0.f) ? h2 : expm1f(h2);
  o.w = (h3 > 0.f) ? h3 : expm1f(h3);
  *(float4*)(out + (size_t)row * DD + c4) = o;
}

// ---------------------------------------------------------------------------
extern "C" void kernel_launch(void* const* d_in, const int* in_sizes, int n_in,
                              void* d_out, int out_size) {
  const float* inp = (const float*)d_in[0];
  const int* adj = (const int*)d_in[1];
  const float* W = (const float*)d_in[2];
  const float* W2 = (const float*)d_in[3];
  const float* W3 = (const float*)d_in[4];
  float* out = (float*)d_out;

  split_kernel<<<4288, 256>>>(inp, W, W2, W3);

  cudaFuncSetAttribute(proj_kernel, cudaFuncAttributeMaxDynamicSharedMemorySize,
                       PSMEM);
  proj_kernel<<<dim3(NN / 64, 3), 128, PSMEM>>>();

  cudaFuncSetAttribute(attn_kernel, cudaFuncAttributeMaxDynamicSharedMemorySize,
                       SMEM_BYTES);
  attn_kernel<<<dim3(NN / BM, SPLITS), 256, SMEM_BYTES>>>(adj);

  reduce_kernel<<<(NN * DD) / 1024, 256>>>(out);
}

// round 14
// speedup vs baseline: 2.5108x; 1.3246x over previous
#include <cuda_runtime.h>
#include <cuda_fp16.h>
#include <math.h>
#include <stdint.h>

#define NN 8192
#define FIN 256
#define DD 128
#define ALPHA 0.2f
#define SPLITS 16
#define BM 128
#define BN 64
#define TILES ((NN / SPLITS) / BN)   // 8
#define LOG2E 1.44269504f
#define MASKV (-100000.f)

// Scratch (allocation-free rule: __device__ globals).
// H,K: fp16 hi/lo packed planes; V: single fp16 plane. 16 uint4/row = 128 fp16.
__device__ uint4 gHh[(size_t)NN * 16];
__device__ uint4 gHl[(size_t)NN * 16];
__device__ uint4 gKh[(size_t)NN * 16];
__device__ uint4 gKl[(size_t)NN * 16];
__device__ uint4 gV[(size_t)NN * 16];
// inp split planes: 8192 x 256 -> 128 words/row.
__device__ uint4 gIh[(size_t)NN * 32];
__device__ uint4 gIl[(size_t)NN * 32];
// W split planes: 3 mats x 256 rows x 64 words.
__device__ uint4 gWh[3 * 256 * 16];
__device__ uint4 gWl[3 * 256 * 16];
__device__ float gNum[(size_t)SPLITS * NN * DD];
__device__ float gDen[(size_t)SPLITS * NN];
__device__ float gM[(size_t)SPLITS * NN];   // running max, log2 units

// ---------------------------------------------------------------------------
// helpers
// ---------------------------------------------------------------------------
__device__ __forceinline__ uint32_t smem_u32(const void* p) {
  uint32_t a;
  asm("{ .reg .u64 t; cvta.to.shared.u64 t, %1; cvt.u32.u64 %0, t; }"
      : "=r"(a) : "l"(p));
  return a;
}
__device__ __forceinline__ uint32_t pack_h2(float a, float b) {
  __half2 r = __floats2half2_rn(a, b);
  return *reinterpret_cast<uint32_t*>(&r);
}
__device__ __forceinline__ float h_round(float x) {
  return __half2float(__float2half_rn(x));
}
__device__ __forceinline__ float ex2f(float x) {
  float r;
  asm("ex2.approx.f32 %0, %1;" : "=f"(r) : "f"(x));
  return r;
}

#define LDSM_X4(r0, r1, r2, r3, a)                                            \
  asm volatile("ldmatrix.sync.aligned.m8n8.x4.shared.b16 {%0,%1,%2,%3}, [%4];"\
               : "=r"(r0), "=r"(r1), "=r"(r2), "=r"(r3) : "r"(a))
#define LDSM_X4T(r0, r1, r2, r3, a)                                           \
  asm volatile("ldmatrix.sync.aligned.m8n8.x4.trans.shared.b16 {%0,%1,%2,%3}, [%4];" \
               : "=r"(r0), "=r"(r1), "=r"(r2), "=r"(r3) : "r"(a))

__device__ __forceinline__ void mma_f16(float* d, const uint32_t* a,
                                        uint32_t b0, uint32_t b1) {
  asm volatile(
      "mma.sync.aligned.m16n8k16.row.col.f32.f16.f16.f32 "
      "{%0,%1,%2,%3}, {%4,%5,%6,%7}, {%8,%9}, {%0,%1,%2,%3};"
      : "+f"(d[0]), "+f"(d[1]), "+f"(d[2]), "+f"(d[3])
      : "r"(a[0]), "r"(a[1]), "r"(a[2]), "r"(a[3]), "r"(b0), "r"(b1));
}

__device__ __forceinline__ void cp16(uint32_t dst, const void* src) {
  asm volatile("cp.async.cg.shared.global [%0], [%1], 16;" :: "r"(dst), "l"(src));
}
#define CP_COMMIT() asm volatile("cp.async.commit_group;" ::: "memory")
#define CP_WAIT1()  asm volatile("cp.async.wait_group 1;" ::: "memory")

// ---------------------------------------------------------------------------
// Kernel 0: split fp32 inputs into packed fp16 hi/lo planes (inp + W).
// ---------------------------------------------------------------------------
__global__ __launch_bounds__(256) void split_kernel(
    const float* __restrict__ inp, const float* __restrict__ W0,
    const float* __restrict__ W1, const float* __restrict__ W2) {
  int idx = blockIdx.x * 256 + threadIdx.x;
  const float* src;
  uint32_t* dh;
  uint32_t* dl;
  int off;
  if (idx < 1048576) {
    src = inp; off = idx;
    dh = (uint32_t*)gIh; dl = (uint32_t*)gIl;
  } else {
    int j = idx - 1048576;
    int mat = j / 16384;
    off = j % 16384;
    src = (mat == 0) ? W0 : (mat == 1) ? W1 : W2;
    dh = (uint32_t*)gWh + mat * 16384;
    dl = (uint32_t*)gWl + mat * 16384;
  }
  float2 v = *(const float2*)(src + 2 * (size_t)off);
  float h0 = h_round(v.x);
  float h1 = h_round(v.y);
  dh[off] = pack_h2(h0, h1);
  dl[off] = pack_h2(v.x - h0, v.y - h1);
}

// ---------------------------------------------------------------------------
// Kernel A: projections via warp mma.sync fp16 hi/lo (3-term).
// mat 0/1 (H/K): epilogue writes fp16 hi/lo planes.
// mat 2 (V): epilogue writes single fp16 plane.
// ---------------------------------------------------------------------------
#define PSTG 27648
#define PSMEM 55296
__global__ void __launch_bounds__(128, 1) proj_kernel() {
  extern __shared__ char smem[];
  uint32_t sb = smem_u32(smem);
  int t = threadIdx.x, w = t >> 5, lane = t & 31;
  int g = lane >> 2, tig = lane & 3;
  int q = lane >> 3, r = lane & 7;
  int rowbase = blockIdx.x * 64;
  int mat = blockIdx.y;
  const uint4* Wh = gWh + mat * 256 * 16;
  const uint4* Wl = gWl + mat * 256 * 16;

  uint32_t offA = (uint32_t)((w * 16 + (q & 1) * 8 + r) * 80 + (q >> 1) * 16);
  uint32_t offB = (uint32_t)(10240 + ((q & 1) * 8 + r) * 272 + (q >> 1) * 16);

  auto load_chunk = [&](int s, int c) {
    uint32_t base = sb + (uint32_t)(s * PSTG);
#pragma unroll
    for (int i = 0; i < 4; i++) {
      int idx = t + i * 128;
      int plane = idx >> 8, row = (idx >> 2) & 63, ch = idx & 3;
      const uint4* srcp = (plane ? gIl : gIh) + (size_t)(rowbase + row) * 32 + c * 4 + ch;
      cp16(base + plane * 5120 + row * 80 + ch * 16, srcp);
    }
#pragma unroll
    for (int i = 0; i < 8; i++) {
      int idx = t + i * 128;
      int plane = idx >> 9, row = (idx >> 4) & 31, ch = idx & 15;
      const uint4* srcp = (plane ? Wl : Wh) + (size_t)(c * 32 + row) * 16 + ch;
      cp16(base + 10240 + plane * 8704 + row * 272 + ch * 16, srcp);
    }
  };

  load_chunk(0, 0); CP_COMMIT();
  load_chunk(1, 1); CP_COMMIT();

  float oacc[16][4];
#pragma unroll
  for (int c = 0; c < 16; c++)
#pragma unroll
    for (int k = 0; k < 4; k++) oacc[c][k] = 0.f;

  for (int c = 0; c < 8; c++) {
    int s = c & 1;
    CP_WAIT1();
    __syncthreads();
    uint32_t aA = sb + (uint32_t)(s * PSTG) + offA;
    uint32_t aB = sb + (uint32_t)(s * PSTG) + offB;
#pragma unroll
    for (int kk = 0; kk < 2; kk++) {
      uint32_t ah[4], al[4];
      LDSM_X4(ah[0], ah[1], ah[2], ah[3], aA + kk * 32);
      LDSM_X4(al[0], al[1], al[2], al[3], aA + 5120 + kk * 32);
#pragma unroll
      for (int np = 0; np < 8; np++) {
        uint32_t bh[4], bl[4];
        uint32_t boff = (uint32_t)(kk * 4352 + np * 32);
        LDSM_X4T(bh[0], bh[1], bh[2], bh[3], aB + boff);
        LDSM_X4T(bl[0], bl[1], bl[2], bl[3], aB + 8704 + boff);
        mma_f16(oacc[2 * np], ah, bh[0], bh[1]);
        mma_f16(oacc[2 * np], ah, bl[0], bl[1]);
        mma_f16(oacc[2 * np], al, bh[0], bh[1]);
        mma_f16(oacc[2 * np + 1], ah, bh[2], bh[3]);
        mma_f16(oacc[2 * np + 1], ah, bl[2], bl[3]);
        mma_f16(oacc[2 * np + 1], al, bh[2], bh[3]);
      }
    }
    __syncthreads();
    if (c + 2 < 8) load_chunk(s, c + 2);
    CP_COMMIT();
  }

  int row0 = rowbase + w * 16 + g;
  size_t r0w = (size_t)row0 * 64;
  size_t r8w = r0w + 8 * 64;
  if (mat == 2) {
    uint32_t* Pv = (uint32_t*)gV;
#pragma unroll
    for (int np = 0; np < 8; np++) {
#pragma unroll
      for (int half = 0; half < 2; half++) {
        float* d = oacc[2 * np + half];
        int word = np * 8 + half * 4 + tig;
        Pv[r0w + word] = pack_h2(d[0], d[1]);
        Pv[r8w + word] = pack_h2(d[2], d[3]);
      }
    }
  } else {
    uint32_t* Ph = (uint32_t*)(mat ? gKh : gHh);
    uint32_t* Pl = (uint32_t*)(mat ? gKl : gHl);
#pragma unroll
    for (int np = 0; np < 8; np++) {
#pragma unroll
      for (int half = 0; half < 2; half++) {
        float* d = oacc[2 * np + half];
        int word = np * 8 + half * 4 + tig;
        float h0 = h_round(d[0]);
        float h1 = h_round(d[1]);
        float h2 = h_round(d[2]);
        float h3 = h_round(d[3]);
        Ph[r0w + word] = pack_h2(h0, h1);
        Pl[r0w + word] = pack_h2(d[0] - h0, d[1] - h1);
        Ph[r8w + word] = pack_h2(h2, h3);
        Pl[r8w + word] = pack_h2(d[2] - h2, d[3] - h3);
      }
    }
  }
}

// ---------------------------------------------------------------------------
// Kernel B: fused attention, fp16. S = 3-term hi/lo (192 MMA/tile),
// log2-domain online-max softmax, PV single-term (64 MMA/tile),
// den via constant-ones-B MMA (4 MMA/tile).
// Stage: Khi 0 / Klo 17408 / V 34816; 64 rows, stride 272; stage 52224.
// ---------------------------------------------------------------------------
#define TRS 272
#define STAGE 52224
#define SMEM_BYTES 156672           // 3 stages

__device__ __forceinline__ void load_kv_async(uint32_t sb, int s, int cb, int t) {
  uint32_t base = sb + (uint32_t)(s * STAGE);
#pragma unroll
  for (int i = 0; i < 12; i++) {
    int idx = t + i * 256;                 // 0..3071
    if (idx < 2048) {
      int plane = idx >> 10, row = (idx >> 4) & 63, ch = idx & 15;
      const uint4* src = (plane ? gKl : gKh) + (size_t)(cb + row) * 16 + ch;
      cp16(base + plane * 17408 + row * TRS + ch * 16, src);
    } else {
      int v = idx - 2048;
      int row = (v >> 4) & 63, ch = v & 15;
      cp16(base + 34816 + row * TRS + ch * 16, gV + (size_t)(cb + row) * 16 + ch);
    }
  }
}

__global__ void __launch_bounds__(256, 1) attn_kernel(const int* __restrict__ adj) {
  extern __shared__ char smem[];
  uint32_t sb = smem_u32(smem);
  int t = threadIdx.x, w = t >> 5, lane = t & 31;
  int g = lane >> 2, tig = lane & 3;
  int rowbase = blockIdx.x * BM;
  int colstart = blockIdx.y * (NN / SPLITS);
  int q = lane >> 3, r = lane & 7;
  uint32_t offB = (uint32_t)(((q >> 1) * 8 + r) * TRS + (q & 1) * 16);
  uint32_t offV = (uint32_t)(34816 + ((q & 1) * 8 + r) * TRS + (q >> 1) * 16);
  int row0 = rowbase + w * 16 + g;

  // constant B fragment for the all-ones den column (col 0 lives in lanes 0-3)
  uint32_t bones = (lane < 4) ? 0x3C003C00u : 0u;

  load_kv_async(sb, 0, colstart, t);
  CP_COMMIT();
  load_kv_async(sb, 1, colstart + BN, t);
  CP_COMMIT();

  // H fragments via direct LDG (A-fragment layout == packed word layout)
  uint32_t ahf[8][4], alf[8][4];
  {
    const uint32_t* Hh = (const uint32_t*)gHh;
    const uint32_t* Hl = (const uint32_t*)gHl;
    size_t b0 = (size_t)row0 * 64;
    size_t b8 = b0 + 8 * 64;
#pragma unroll
    for (int kk = 0; kk < 8; kk++) {
      int wd = kk * 8 + tig;
      ahf[kk][0] = Hh[b0 + wd];     ahf[kk][1] = Hh[b8 + wd];
      ahf[kk][2] = Hh[b0 + wd + 4]; ahf[kk][3] = Hh[b8 + wd + 4];
      alf[kk][0] = Hl[b0 + wd];     alf[kk][1] = Hl[b8 + wd];
      alf[kk][2] = Hl[b0 + wd + 4]; alf[kk][3] = Hl[b8 + wd + 4];
    }
  }

  float oacc[16][4];
#pragma unroll
  for (int c = 0; c < 16; c++)
#pragma unroll
    for (int k = 0; k < 4; k++) oacc[c][k] = 0.f;
  float dacc[4] = {0.f, 0.f, 0.f, 0.f};
  float m0 = -90000.f, m1 = -90000.f;     // running max, log2 units

  const int* arow0 = adj + (size_t)row0 * NN;
  const int* arow1 = arow0 + (size_t)8 * NN;

  int s3 = 0;
  for (int tt = 0; tt < TILES; tt++) {
    int cb = colstart + tt * BN;
    CP_WAIT1();
    __syncthreads();
    if (tt + 2 < TILES) load_kv_async(sb, (tt + 2) % 3, colstart + (tt + 2) * BN, t);
    CP_COMMIT();

    // adj prefetch (hidden under S MMAs)
    int2 am[16];
#pragma unroll
    for (int n = 0; n < 8; n++) {
      am[n] = *(const int2*)(arow0 + cb + n * 8 + 2 * tig);
      am[n + 8] = *(const int2*)(arow1 + cb + n * 8 + 2 * tig);
    }

    uint32_t aBh = sb + (uint32_t)(s3 * STAGE) + offB;
    uint32_t aBl = aBh + 17408;
    uint32_t aVh = sb + (uint32_t)(s3 * STAGE) + offV;

    // ---- S = H @ K^T (fp16 hi/lo: hh + hl + lh), A from registers ----
    float sacc[8][4];
#pragma unroll
    for (int c = 0; c < 8; c++)
#pragma unroll
      for (int k = 0; k < 4; k++) sacc[c][k] = 0.f;

#pragma unroll
    for (int kk = 0; kk < 8; kk++) {
#pragma unroll
      for (int np = 0; np < 4; np++) {
        uint32_t bh[4], bl[4];
        uint32_t boff = (uint32_t)(np * (16 * TRS) + kk * 32);
        LDSM_X4(bh[0], bh[1], bh[2], bh[3], aBh + boff);
        LDSM_X4(bl[0], bl[1], bl[2], bl[3], aBl + boff);
        mma_f16(sacc[2 * np], ahf[kk], bh[0], bh[1]);
        mma_f16(sacc[2 * np], ahf[kk], bl[0], bl[1]);
        mma_f16(sacc[2 * np], alf[kk], bh[0], bh[1]);
        mma_f16(sacc[2 * np + 1], ahf[kk], bh[2], bh[3]);
        mma_f16(sacc[2 * np + 1], ahf[kk], bl[2], bl[3]);
        mma_f16(sacc[2 * np + 1], alf[kk], bh[2], bh[3]);
      }
    }

    // ---- leakyrelu + mask -> log2 args (in place); online max; rescale ----
#pragma unroll
    for (int n = 0; n < 8; n++) {
      int2 mA = am[n];
      int2 mB = am[n + 8];
      float s0 = sacc[n][0], s1 = sacc[n][1], s2 = sacc[n][2], s3v = sacc[n][3];
      float a0 = fmaxf(s0, ALPHA * s0) * LOG2E;
      float a1 = fmaxf(s1, ALPHA * s1) * LOG2E;
      float a2 = fmaxf(s2, ALPHA * s2) * LOG2E;
      float a3 = fmaxf(s3v, ALPHA * s3v) * LOG2E;
      sacc[n][0] = (mA.x > 0) ? a0 : MASKV;
      sacc[n][1] = (mA.y > 0) ? a1 : MASKV;
      sacc[n][2] = (mB.x > 0) ? a2 : MASKV;
      sacc[n][3] = (mB.y > 0) ? a3 : MASKV;
    }
    {
      float mt0 = MASKV, mt1 = MASKV;
#pragma unroll
      for (int n = 0; n < 8; n++) {
        mt0 = fmaxf(mt0, fmaxf(sacc[n][0], sacc[n][1]));
        mt1 = fmaxf(mt1, fmaxf(sacc[n][2], sacc[n][3]));
      }
      mt0 = fmaxf(mt0, __shfl_xor_sync(0xffffffffu, mt0, 1));
      mt0 = fmaxf(mt0, __shfl_xor_sync(0xffffffffu, mt0, 2));
      mt1 = fmaxf(mt1, __shfl_xor_sync(0xffffffffu, mt1, 1));
      mt1 = fmaxf(mt1, __shfl_xor_sync(0xffffffffu, mt1, 2));
      float m0n = fmaxf(m0, mt0);
      float m1n = fmaxf(m1, mt1);
      bool need = (m0n > m0) || (m1n > m1);
      if (__any_sync(0xffffffffu, need)) {
        float sc0 = ex2f(m0 - m0n);
        float sc1 = ex2f(m1 - m1n);
#pragma unroll
        for (int c = 0; c < 16; c++) {
          oacc[c][0] *= sc0; oacc[c][1] *= sc0;
          oacc[c][2] *= sc1; oacc[c][3] *= sc1;
        }
        dacc[0] *= sc0; dacc[2] *= sc1;
      }
      m0 = m0n; m1 = m1n;
    }

    // ---- P = ex2(arg - m) -> fp16 fragments -> den MMA + PV ----
#pragma unroll
    for (int kk = 0; kk < 4; kk++) {
      uint32_t pw[4];
#pragma unroll
      for (int cp = 0; cp < 2; cp++) {
        int n = 2 * kk + cp;
        float p0 = ex2f(sacc[n][0] - m0);
        float p1 = ex2f(sacc[n][1] - m0);
        float p2 = ex2f(sacc[n][2] - m1);
        float p3 = ex2f(sacc[n][3] - m1);
        pw[2 * cp + 0] = pack_h2(p0, p1);
        pw[2 * cp + 1] = pack_h2(p2, p3);
      }
      mma_f16(dacc, pw, bones, bones);   // den += P @ ones (col 0)
#pragma unroll
      for (int cp = 0; cp < 8; cp++) {
        uint32_t vv[4];
        uint32_t voff = (uint32_t)(kk * (16 * TRS) + cp * 32);
        LDSM_X4T(vv[0], vv[1], vv[2], vv[3], aVh + voff);
        mma_f16(oacc[2 * cp], pw, vv[0], vv[1]);
        mma_f16(oacc[2 * cp + 1], pw, vv[2], vv[3]);
      }
    }
    s3 = (s3 == 2) ? 0 : s3 + 1;
  }

  // ---- epilogue: den (col 0 lives in tig==0 lanes) + m + O partials ----
  if (tig == 0) {
    gDen[(size_t)blockIdx.y * NN + row0] = dacc[0];
    gDen[(size_t)blockIdx.y * NN + row0 + 8] = dacc[2];
    gM[(size_t)blockIdx.y * NN + row0] = m0;
    gM[(size_t)blockIdx.y * NN + row0 + 8] = m1;
  }
  float* base0 = gNum + ((size_t)blockIdx.y * NN + row0) * DD;
  float* base1 = base0 + (size_t)8 * DD;
#pragma unroll
  for (int c = 0; c < 16; c++) {
    *(float2*)(base0 + c * 8 + 2 * tig) = make_float2(oacc[c][0], oacc[c][1]);
    *(float2*)(base1 + c * 8 + 2 * tig) = make_float2(oacc[c][2], oacc[c][3]);
  }
}

// ---------------------------------------------------------------------------
// Kernel C: combine split partials with per-split max weights (log2 domain),
// divide, ELU.
// ---------------------------------------------------------------------------
__global__ __launch_bounds__(256) void reduce_kernel(float* __restrict__ out) {
  int idx = blockIdx.x * 256 + threadIdx.x;
  int row = idx >> 5;
  int c4 = (idx & 31) * 4;
  float ms[SPLITS];
  float M = -1e30f;
#pragma unroll
  for (int s = 0; s < SPLITS; s++) {
    ms[s] = gM[(size_t)s * NN + row];
    M = fmaxf(M, ms[s]);
  }
  float4 num = make_float4(0.f, 0.f, 0.f, 0.f);
  float den = 0.f;
#pragma unroll
  for (int s = 0; s < SPLITS; s++) {
    float wgt = ex2f(ms[s] - M);
    float4 v = *(const float4*)(gNum + ((size_t)s * NN + row) * DD + c4);
    num.x += v.x * wgt; num.y += v.y * wgt;
    num.z += v.z * wgt; num.w += v.w * wgt;
    den += gDen[(size_t)s * NN + row] * wgt;
  }
  float inv = 1.f / den;
  float h0 = num.x * inv, h1 = num.y * inv, h2 = num.z * inv, h3 = num.w * inv;
  float4 o;
  o.x = (h0 > 0.f) ? h0 : expm1f(h0);
  o.y = (h1 > 0.f) ? h1 : expm1f(h1);
  o.z = (h2 > 0.f) ? h2 : expm1f(h2);
  o.w = (h3 > 0.f) ? h3 : expm1f(h3);
  *(float4*)(out + (size_t)row * DD + c4) = o;
}

// ---------------------------------------------------------------------------
extern "C" void kernel_launch(void* const* d_in, const int* in_sizes, int n_in,
                              void* d_out, int out_size) {
  const float* inp = (const float*)d_in[0];
  const int* adj = (const int*)d_in[1];
  const float* W = (const float*)d_in[2];
  const float* W2 = (const float*)d_in[3];
  const float* W3 = (const float*)d_in[4];
  float* out = (float*)d_out;

  split_kernel<<<4288, 256>>>(inp, W, W2, W3);

  cudaFuncSetAttribute(proj_kernel, cudaFuncAttributeMaxDynamicSharedMemorySize,
                       PSMEM);
  proj_kernel<<<dim3(NN / 64, 3), 128, PSMEM>>>();

  cudaFuncSetAttribute(attn_kernel, cudaFuncAttributeMaxDynamicSharedMemorySize,
                       SMEM_BYTES);
  attn_kernel<<<dim3(NN / BM, SPLITS), 256, SMEM_BYTES>>>(adj);

  reduce_kernel<<<(NN * DD) / 1024, 256>>>(out);
}